// round 1
// baseline (speedup 1.0000x reference)
#include <cuda_runtime.h>
#include <cuda_bf16.h>
#include <cstdint>

#define NS   25
#define NQ   200
#define FF   80
#define DD   512
#define WAY  5
#define KT   64      // K tile (bf16 elems)
#define PITCH 72     // SMEM row pitch in bf16 (64 data + 8 pad -> conflict-free ldmatrix)

// Scratch (allocation-free rule: __device__ globals)
__device__ __nv_bfloat16 g_Sn[NS * FF * DD];   // 2 MB
__device__ __nv_bfloat16 g_Qn[NQ * FF * DD];   // 16 MB
__device__ float         g_cum[NS * NQ];

// ---------------------------------------------------------------------------
// Kernel 1: L2-normalize each D=512 feature row, gather global/local concat,
// convert to bf16. One warp per row.
// ---------------------------------------------------------------------------
__global__ void normalize_kernel(const float* __restrict__ sg, const float* __restrict__ sl,
                                 const float* __restrict__ qg, const float* __restrict__ ql)
{
    int warp = (blockIdx.x * blockDim.x + threadIdx.x) >> 5;
    int lane = threadIdx.x & 31;
    const int total = (NS + NQ) * FF;
    if (warp >= total) return;

    const float* src;
    __nv_bfloat16* dst;
    if (warp < NS * FF) {
        int s = warp / FF, f = warp % FF;
        src = (f < 16) ? sg + (size_t)(s * 16 + f) * DD
                       : sl + (size_t)(s * 64 + (f - 16)) * DD;
        dst = g_Sn + (size_t)warp * DD;
    } else {
        int r = warp - NS * FF;
        int q = r / FF, f = r % FF;
        src = (f < 16) ? qg + (size_t)(q * 16 + f) * DD
                       : ql + (size_t)(q * 64 + (f - 16)) * DD;
        dst = g_Qn + (size_t)r * DD;
    }

    float4 v[4];
    float ss = 0.f;
    const float4* s4 = reinterpret_cast<const float4*>(src);
#pragma unroll
    for (int i = 0; i < 4; i++) {
        v[i] = s4[lane + 32 * i];
        ss += v[i].x * v[i].x + v[i].y * v[i].y + v[i].z * v[i].z + v[i].w * v[i].w;
    }
#pragma unroll
    for (int o = 16; o; o >>= 1) ss += __shfl_xor_sync(0xFFFFFFFFu, ss, o);
    float rn = rsqrtf(fmaxf(ss, 1e-24f));   // 1/max(||x||,eps)

    __nv_bfloat162* d2 = reinterpret_cast<__nv_bfloat162*>(dst);
#pragma unroll
    for (int i = 0; i < 4; i++) {
        __nv_bfloat162 lo = __floats2bfloat162_rn(v[i].x * rn, v[i].y * rn);
        __nv_bfloat162 hi = __floats2bfloat162_rn(v[i].z * rn, v[i].w * rn);
        d2[2 * (lane + 32 * i) + 0] = lo;
        d2[2 * (lane + 32 * i) + 1] = hi;
    }
}

// ---------------------------------------------------------------------------
// Kernel 2: one CTA per (s,q) pair. Computes the 80x80 sim block via bf16
// mma.sync (fp32 accum), reduces Sum(sim) and Sum(sim^2), writes cum[s,q].
// 5 warps: warp w owns rows [16w,16w+16) x all 80 cols.
// ---------------------------------------------------------------------------
__device__ __forceinline__ void ldsm_x4(uint32_t (&r)[4], uint32_t addr) {
    asm volatile("ldmatrix.sync.aligned.m8n8.x4.shared.b16 {%0,%1,%2,%3}, [%4];"
                 : "=r"(r[0]), "=r"(r[1]), "=r"(r[2]), "=r"(r[3]) : "r"(addr));
}

__device__ __forceinline__ void mma16816(float (&d)[4], const uint32_t (&a)[4],
                                         uint32_t b0, uint32_t b1) {
    asm volatile("mma.sync.aligned.m16n8k16.row.col.f32.bf16.bf16.f32 "
                 "{%0,%1,%2,%3},{%4,%5,%6,%7},{%8,%9},{%0,%1,%2,%3};"
                 : "+f"(d[0]), "+f"(d[1]), "+f"(d[2]), "+f"(d[3])
                 : "r"(a[0]), "r"(a[1]), "r"(a[2]), "r"(a[3]), "r"(b0), "r"(b1));
}

__global__ void __launch_bounds__(160) pair_kernel()
{
    __shared__ __nv_bfloat16 sA[2][FF * PITCH];
    __shared__ __nv_bfloat16 sB[2][FF * PITCH];
    __shared__ float red1[5], red2[5];

    const int q = blockIdx.x;
    const int s = blockIdx.y;
    const __nv_bfloat16* gA = g_Sn + (size_t)s * FF * DD;
    const __nv_bfloat16* gB = g_Qn + (size_t)q * FF * DD;

    const int tid  = threadIdx.x;
    const int lane = tid & 31;
    const int warp = tid >> 5;

    // --- async tile loader: 80 rows x 64 bf16 = 640 x 16B chunks per matrix ---
    auto load_tile = [&](int buf, int kt) {
#pragma unroll
        for (int i = 0; i < 4; i++) {
            int ch  = tid + 160 * i;
            int row = ch >> 3, cc = ch & 7;
            const __nv_bfloat16* ga = gA + (size_t)row * DD + kt * KT + cc * 8;
            const __nv_bfloat16* gb = gB + (size_t)row * DD + kt * KT + cc * 8;
            uint32_t sa = (uint32_t)__cvta_generic_to_shared(&sA[buf][row * PITCH + cc * 8]);
            uint32_t sb = (uint32_t)__cvta_generic_to_shared(&sB[buf][row * PITCH + cc * 8]);
            asm volatile("cp.async.cg.shared.global [%0], [%1], 16;" :: "r"(sa), "l"(ga));
            asm volatile("cp.async.cg.shared.global [%0], [%1], 16;" :: "r"(sb), "l"(gb));
        }
    };

    float acc[10][4];
#pragma unroll
    for (int n = 0; n < 10; n++)
#pragma unroll
        for (int i = 0; i < 4; i++) acc[n][i] = 0.f;

    load_tile(0, 0); asm volatile("cp.async.commit_group;");
    load_tile(1, 1); asm volatile("cp.async.commit_group;");

    // ldmatrix lane-address components
    const int m0 = warp * 16;
    const int a_row    = m0 + (lane & 15);
    const int a_coloff = (lane >> 4) << 3;
    const int b_row    = (lane & 7) + ((lane >> 4) << 3);
    const int b_coloff = ((lane >> 3) & 1) << 3;

    for (int kt = 0; kt < DD / KT; kt++) {
        asm volatile("cp.async.wait_group 1;");
        __syncthreads();
        const int buf = kt & 1;
        const __nv_bfloat16* A = sA[buf];
        const __nv_bfloat16* B = sB[buf];

#pragma unroll
        for (int k16 = 0; k16 < KT / 16; k16++) {
            const int kb = k16 * 16;
            uint32_t a[4];
            ldsm_x4(a, (uint32_t)__cvta_generic_to_shared(&A[a_row * PITCH + kb + a_coloff]));
#pragma unroll
            for (int nt = 0; nt < 5; nt++) {
                uint32_t b[4];
                ldsm_x4(b, (uint32_t)__cvta_generic_to_shared(
                            &B[(nt * 16 + b_row) * PITCH + kb + b_coloff]));
                mma16816(acc[2 * nt + 0], a, b[0], b[1]);
                mma16816(acc[2 * nt + 1], a, b[2], b[3]);
            }
        }
        __syncthreads();
        if (kt + 2 < DD / KT) load_tile(buf, kt + 2);
        asm volatile("cp.async.commit_group;");
    }

    // --- reduce Sum(sim), Sum(sim^2) across all 6400 elements ---
    float s1 = 0.f, s2 = 0.f;
#pragma unroll
    for (int n = 0; n < 10; n++)
#pragma unroll
        for (int i = 0; i < 4; i++) {
            float v = acc[n][i];
            s1 += v;
            s2 += v * v;
        }
#pragma unroll
    for (int o = 16; o; o >>= 1) {
        s1 += __shfl_xor_sync(0xFFFFFFFFu, s1, o);
        s2 += __shfl_xor_sync(0xFFFFFFFFu, s2, o);
    }
    if (lane == 0) { red1[warp] = s1; red2[warp] = s2; }
    __syncthreads();
    if (tid == 0) {
        float S1 = 0.f, S2 = 0.f;
#pragma unroll
        for (int w = 0; w < 5; w++) { S1 += red1[w]; S2 += red2[w]; }
        // cum = 2 * sum_{ij} (1 - sim)^2 = 2*(F*F - 2*S1 + S2)
        g_cum[s * NQ + q] = 2.f * ((float)(FF * FF) - 2.f * S1 + S2);
    }
}

// ---------------------------------------------------------------------------
// Kernel 3: class-mean over support rows, logits = -class_dists^T
// ---------------------------------------------------------------------------
__global__ void logits_kernel(const long long* __restrict__ labels, float* __restrict__ out)
{
    int q = blockIdx.x * blockDim.x + threadIdx.x;
    if (q >= NQ) return;
    float sum[WAY] = {0.f, 0.f, 0.f, 0.f, 0.f};
    float cnt[WAY] = {0.f, 0.f, 0.f, 0.f, 0.f};
#pragma unroll
    for (int s = 0; s < NS; s++) {
        int c = (int)labels[s];
        sum[c] += g_cum[s * NQ + q];
        cnt[c] += 1.f;
    }
#pragma unroll
    for (int c = 0; c < WAY; c++)
        out[q * WAY + c] = (cnt[c] > 0.f) ? (-sum[c] / cnt[c]) : 0.f;
}

// ---------------------------------------------------------------------------
extern "C" void kernel_launch(void* const* d_in, const int* in_sizes, int n_in,
                              void* d_out, int out_size)
{
    const float*     sg  = (const float*)d_in[0];
    const float*     sl  = (const float*)d_in[1];
    const long long* lab = (const long long*)d_in[2];
    const float*     qg  = (const float*)d_in[3];
    const float*     ql  = (const float*)d_in[4];
    float*           out = (float*)d_out;

    const int rows = (NS + NQ) * FF;                 // 18000 rows, 1 warp each
    normalize_kernel<<<(rows * 32 + 255) / 256, 256>>>(sg, sl, qg, ql);

    dim3 grid(NQ, NS);                                // 5000 pairs
    pair_kernel<<<grid, 160>>>();

    logits_kernel<<<1, 256>>>(lab, out);
}

// round 2
// speedup vs baseline: 1.2539x; 1.2539x over previous
#include <cuda_runtime.h>
#include <cuda_fp16.h>
#include <cstdint>

#define NS     25
#define NQ     200
#define NITEM  (NS + NQ)       // 225
#define FF     80
#define DD     512
#define WAY    5
#define BLK    128              // gram block edge
#define NBLK   10               // packed upper-tri 128x128 blocks of 4x4 grid
#define BLKSZ  (BLK * BLK)      // 16384
#define KPACK  (NBLK * BLKSZ)   // 163840
#define PITCH  136              // smem pitch in halves: conflict-free ldmatrix.trans

// -------- scratch (__device__ globals; no allocations allowed) --------------
__device__ __half g_Sn[NS * FF * DD];        // 2 MB   normalized supports
__device__ __half g_Qn[NQ * FF * DD];        // 16.4MB normalized queries
__device__ float  g_bar[NITEM][DD];          // per-item feature-row sums
__device__ float  g_sbarsum[WAY][DD];        // class-summed support row-sums
__device__ int    g_cls_cnt[WAY];
__device__ int    g_cls_sup[WAY][NS];
__device__ __half g_Gp[WAY][KPACK];          // packed class Grams (x2 off-diag)
__device__ __half g_Hp[NQ][KPACK];           // packed query Grams
__device__ float  g_S2[WAY][NQ];             // sum over class of <G_s, H_q>

__constant__ int c_bi[NBLK] = {0,0,0,0,1,1,1,2,2,3};
__constant__ int c_bj[NBLK] = {0,1,2,3,1,2,3,2,3,3};

// ---------------------------------------------------------------------------
// K1: L2-normalize each D=512 feature row (concat global/local), store fp16.
// One warp per row.
// ---------------------------------------------------------------------------
__global__ void normalize_kernel(const float* __restrict__ sg, const float* __restrict__ sl,
                                 const float* __restrict__ qg, const float* __restrict__ ql)
{
    int warp = (blockIdx.x * blockDim.x + threadIdx.x) >> 5;
    int lane = threadIdx.x & 31;
    if (warp >= NITEM * FF) return;

    const float* src;
    __half* dst;
    if (warp < NS * FF) {
        int s = warp / FF, f = warp % FF;
        src = (f < 16) ? sg + (size_t)(s * 16 + f) * DD
                       : sl + (size_t)(s * 64 + (f - 16)) * DD;
        dst = g_Sn + (size_t)warp * DD;
    } else {
        int r = warp - NS * FF;
        int q = r / FF, f = r % FF;
        src = (f < 16) ? qg + (size_t)(q * 16 + f) * DD
                       : ql + (size_t)(q * 64 + (f - 16)) * DD;
        dst = g_Qn + (size_t)r * DD;
    }

    float4 v[4];
    float ss = 0.f;
    const float4* s4 = reinterpret_cast<const float4*>(src);
#pragma unroll
    for (int i = 0; i < 4; i++) {
        v[i] = s4[lane + 32 * i];
        ss += v[i].x * v[i].x + v[i].y * v[i].y + v[i].z * v[i].z + v[i].w * v[i].w;
    }
#pragma unroll
    for (int o = 16; o; o >>= 1) ss += __shfl_xor_sync(0xFFFFFFFFu, ss, o);
    float rn = rsqrtf(fmaxf(ss, 1e-24f));

    __half2* d2 = reinterpret_cast<__half2*>(dst);
#pragma unroll
    for (int i = 0; i < 4; i++) {
        d2[2 * (lane + 32 * i) + 0] = __floats2half2_rn(v[i].x * rn, v[i].y * rn);
        d2[2 * (lane + 32 * i) + 1] = __floats2half2_rn(v[i].z * rn, v[i].w * rn);
    }
}

// ---------------------------------------------------------------------------
// K2: per-item feature-row sums: bar[item][d] = sum_f X[f][d]
// ---------------------------------------------------------------------------
__global__ void rowsum_kernel()
{
    int item = blockIdx.x;
    int t = threadIdx.x;  // 256 threads, 2 cols each via half2
    const __half2* X = reinterpret_cast<const __half2*>(
        (item < NS) ? g_Sn + (size_t)item * FF * DD
                    : g_Qn + (size_t)(item - NS) * FF * DD);
    float sx = 0.f, sy = 0.f;
#pragma unroll 8
    for (int f = 0; f < FF; f++) {
        float2 v = __half22float2(X[f * (DD / 2) + t]);
        sx += v.x; sy += v.y;
    }
    g_bar[item][2 * t + 0] = sx;
    g_bar[item][2 * t + 1] = sy;
}

// ---------------------------------------------------------------------------
// K3: build class lists from labels, class-summed sbar, zero g_S2
// ---------------------------------------------------------------------------
__global__ void prep_kernel(const long long* __restrict__ labels)
{
    __shared__ int cnt[WAY];
    __shared__ int sup[WAY][NS];
    int t = threadIdx.x;  // 512
    if (t == 0) {
        for (int c = 0; c < WAY; c++) cnt[c] = 0;
        for (int s = 0; s < NS; s++) {
            int c = (int)labels[s];
            sup[c][cnt[c]++] = s;
        }
        for (int c = 0; c < WAY; c++) {
            g_cls_cnt[c] = cnt[c];
            for (int i = 0; i < cnt[c]; i++) g_cls_sup[c][i] = sup[c][i];
        }
    }
    __syncthreads();
    if (t < DD) {
#pragma unroll
        for (int c = 0; c < WAY; c++) {
            float a = 0.f;
            for (int i = 0; i < cnt[c]; i++) a += g_bar[sup[c][i]][t];
            g_sbarsum[c][t] = a;
        }
    }
    for (int i = t; i < WAY * NQ; i += blockDim.x)
        (&g_S2[0][0])[i] = 0.f;
}

// ---------------------------------------------------------------------------
// K4: packed Gram blocks. item 0..4 -> class-summed support Grams (x2 offdiag),
// item 5..204 -> query Grams. One CTA per (block b, item): 128x128 = X_biT X_bj.
// ---------------------------------------------------------------------------
__device__ __forceinline__ void ldsm_x4_t(uint32_t (&r)[4], const __half* p)
{
    uint32_t a = (uint32_t)__cvta_generic_to_shared(p);
    asm volatile("ldmatrix.sync.aligned.m8n8.x4.trans.shared.b16 {%0,%1,%2,%3}, [%4];"
                 : "=r"(r[0]), "=r"(r[1]), "=r"(r[2]), "=r"(r[3]) : "r"(a));
}

__device__ __forceinline__ void mma16816(float (&d)[4], const uint32_t (&a)[4],
                                         uint32_t b0, uint32_t b1)
{
    asm volatile("mma.sync.aligned.m16n8k16.row.col.f32.f16.f16.f32 "
                 "{%0,%1,%2,%3},{%4,%5,%6,%7},{%8,%9},{%0,%1,%2,%3};"
                 : "+f"(d[0]), "+f"(d[1]), "+f"(d[2]), "+f"(d[3])
                 : "r"(a[0]), "r"(a[1]), "r"(a[2]), "r"(a[3]), "r"(b0), "r"(b1));
}

__global__ void __launch_bounds__(256) gram_kernel()
{
    __shared__ __half sX[2][FF * PITCH];   // two 80x128 column-slices of X

    const int b    = blockIdx.x;
    const int item = blockIdx.y;
    const int bi = c_bi[b], bj = c_bj[b];
    const bool diag = (bi == bj);

    const int tid  = threadIdx.x;
    const int lane = tid & 31;
    const int warp = tid >> 5;
    const int m_base = (warp >> 1) * 32;   // 4 row-groups
    const int n_base = (warp & 1) * 64;    // 2 col-groups

    float acc[2][8][4];
#pragma unroll
    for (int mt = 0; mt < 2; mt++)
#pragma unroll
        for (int nt = 0; nt < 8; nt++)
#pragma unroll
            for (int i = 0; i < 4; i++) acc[mt][nt][i] = 0.f;

    const int nsup = (item < WAY) ? g_cls_cnt[item] : 1;
    const __half* pB = diag ? sX[0] : sX[1];
    const int nch = diag ? 1280 : 2560;     // 16B chunks to load

    // ldmatrix.trans per-lane offsets (see fragment derivation)
    const int a_krow = ((lane >> 4) << 3) + (lane & 7);
    const int a_coff = ((lane >> 3) & 1) << 3;
    const int b_krow = (((lane >> 3) & 1) << 3) + (lane & 7);
    const int b_coff = (lane >> 4) << 3;

    for (int si = 0; si < nsup; si++) {
        const __half* base = (item < WAY)
            ? g_Sn + (size_t)g_cls_sup[item][si] * FF * DD
            : g_Qn + (size_t)(item - WAY) * FF * DD;

        for (int ch = tid; ch < nch; ch += 256) {
            int tile = (ch >= 1280) ? 1 : 0;
            int rem  = ch - tile * 1280;
            int r = rem >> 4, cc = rem & 15;
            int colblk = tile ? bj : bi;
            const __half* src = base + (size_t)r * DD + colblk * 128 + cc * 8;
            uint32_t dst = (uint32_t)__cvta_generic_to_shared(&sX[tile][r * PITCH + cc * 8]);
            asm volatile("cp.async.cg.shared.global [%0], [%1], 16;" :: "r"(dst), "l"(src));
        }
        asm volatile("cp.async.commit_group;");
        asm volatile("cp.async.wait_group 0;");
        __syncthreads();

#pragma unroll
        for (int k16 = 0; k16 < FF / 16; k16++) {
            const int k0 = k16 * 16;
            uint32_t a[2][4];
#pragma unroll
            for (int mt = 0; mt < 2; mt++)
                ldsm_x4_t(a[mt], &sX[0][(k0 + a_krow) * PITCH + m_base + mt * 16 + a_coff]);
#pragma unroll
            for (int nt = 0; nt < 4; nt++) {
                uint32_t bf[4];
                ldsm_x4_t(bf, &pB[(k0 + b_krow) * PITCH + n_base + nt * 16 + b_coff]);
#pragma unroll
                for (int mt = 0; mt < 2; mt++) {
                    mma16816(acc[mt][2 * nt + 0], a[mt], bf[0], bf[1]);
                    mma16816(acc[mt][2 * nt + 1], a[mt], bf[2], bf[3]);
                }
            }
        }
        __syncthreads();
    }

    const float scale = (item < WAY && !diag) ? 2.f : 1.f;
    __half* out = ((item < WAY) ? g_Gp[item] : g_Hp[item - WAY]) + b * BLKSZ;
#pragma unroll
    for (int mt = 0; mt < 2; mt++) {
        int r = m_base + mt * 16 + (lane >> 2);
#pragma unroll
        for (int nt = 0; nt < 8; nt++) {
            int c = n_base + nt * 8 + (lane & 3) * 2;
            *(__half2*)(out + r * BLK + c) =
                __floats2half2_rn(acc[mt][nt][0] * scale, acc[mt][nt][1] * scale);
            *(__half2*)(out + (r + 8) * BLK + c) =
                __floats2half2_rn(acc[mt][nt][2] * scale, acc[mt][nt][3] * scale);
        }
    }
}

// ---------------------------------------------------------------------------
// K5: S2[c][q] += <Gp[c], Hp[q]> over packed K = 163840 halves.
// Grid (8 k-chunks, 200 queries), 256 threads, fp32 accumulate.
// ---------------------------------------------------------------------------
__global__ void __launch_bounds__(256) dot_kernel()
{
    const int q  = blockIdx.y;
    const int kc = blockIdx.x;              // 8 chunks of 20480
    const int tid = threadIdx.x;
    const int CH = KPACK / 8;
    const __half* Hq = g_Hp[q] + kc * CH;

    float acc[WAY] = {0.f, 0.f, 0.f, 0.f, 0.f};
#pragma unroll
    for (int i = 0; i < CH / (256 * 8); i++) {      // 10 iters
        int off = (i * 256 + tid) * 8;
        int4 bv = *(const int4*)(Hq + off);
        const __half2* bh = (const __half2*)&bv;
        float2 bf[4];
#pragma unroll
        for (int j = 0; j < 4; j++) bf[j] = __half22float2(bh[j]);
#pragma unroll
        for (int c = 0; c < WAY; c++) {
            int4 av = *(const int4*)(g_Gp[c] + kc * CH + off);
            const __half2* ah = (const __half2*)&av;
#pragma unroll
            for (int j = 0; j < 4; j++) {
                float2 af = __half22float2(ah[j]);
                acc[c] += af.x * bf[j].x + af.y * bf[j].y;
            }
        }
    }
#pragma unroll
    for (int o = 16; o; o >>= 1)
#pragma unroll
        for (int c = 0; c < WAY; c++)
            acc[c] += __shfl_xor_sync(0xFFFFFFFFu, acc[c], o);

    __shared__ float red[8][WAY];
    if ((tid & 31) == 0)
#pragma unroll
        for (int c = 0; c < WAY; c++) red[tid >> 5][c] = acc[c];
    __syncthreads();
    if (tid < WAY) {
        float s = 0.f;
#pragma unroll
        for (int w = 0; w < 8; w++) s += red[w][tid];
        atomicAdd(&g_S2[tid][q], s);
    }
}

// ---------------------------------------------------------------------------
// K6: logits[q][c] = -2*(F^2 - 2*S1sum/cnt + S2sum/cnt). One warp per query.
// ---------------------------------------------------------------------------
__global__ void logits_kernel(float* __restrict__ out)
{
    int warp = (blockIdx.x * blockDim.x + threadIdx.x) >> 5;
    int lane = threadIdx.x & 31;
    if (warp >= NQ) return;
    const int q = warp;

    float s1[WAY] = {0.f, 0.f, 0.f, 0.f, 0.f};
    const float* qb = g_bar[NS + q];
    for (int k = lane; k < DD; k += 32) {
        float qv = qb[k];
#pragma unroll
        for (int c = 0; c < WAY; c++) s1[c] += g_sbarsum[c][k] * qv;
    }
#pragma unroll
    for (int o = 16; o; o >>= 1)
#pragma unroll
        for (int c = 0; c < WAY; c++)
            s1[c] += __shfl_xor_sync(0xFFFFFFFFu, s1[c], o);

    if (lane < WAY) {
        int c = lane;
        float cnt = (float)g_cls_cnt[c];
        float v = -2.f * (float)(FF * FF) + (4.f * s1[c] - 2.f * g_S2[c][q]) / cnt;
        out[q * WAY + c] = v;
    }
}

// ---------------------------------------------------------------------------
extern "C" void kernel_launch(void* const* d_in, const int* in_sizes, int n_in,
                              void* d_out, int out_size)
{
    const float*     sg  = (const float*)d_in[0];
    const float*     sl  = (const float*)d_in[1];
    const long long* lab = (const long long*)d_in[2];
    const float*     qg  = (const float*)d_in[3];
    const float*     ql  = (const float*)d_in[4];
    float*           out = (float*)d_out;

    const int rows = NITEM * FF;                       // 18000 rows
    normalize_kernel<<<(rows * 32 + 255) / 256, 256>>>(sg, sl, qg, ql);
    rowsum_kernel<<<NITEM, 256>>>();
    prep_kernel<<<1, 512>>>(lab);
    gram_kernel<<<dim3(NBLK, WAY + NQ), 256>>>();      // 2050 CTAs
    dot_kernel<<<dim3(8, NQ), 256>>>();                // 1600 CTAs
    logits_kernel<<<(NQ * 32 + 255) / 256, 256>>>(out);
}